// round 3
// baseline (speedup 1.0000x reference)
#include <cuda_runtime.h>
#include <cuda_bf16.h>
#include <cstdint>

// Shapes (fixed by the problem)
#define Bb 8
#define Cc 1024
#define Qq 128
#define Ee 512
#define Hh 1024
#define E4 (4*Ee)   // 2048

// ---------------------------------------------------------------------------
// Scratch (static __device__ arrays — allowed; runtime alloc is not)
// ---------------------------------------------------------------------------
__device__ float g_cw   [Bb*Cc];            // context @ w_context          (8,1024)
__device__ float g_qw   [Bb*Qq];            // question @ w_question        (8,128)
__device__ float g_qmT  [Bb*Ee*Qq];         // (question*w_mult)^T per b    (8,512,128)
__device__ float g_S    [Bb*Cc*Qq];         // sim, then softmax P in-place (8,1024,128)
__device__ float g_m    [Bb*Cc];            // rowmax of sim over q
__device__ float g_alpha[Bb*Cc];            // softmax over c of g_m
__device__ float g_q2c  [Bb*Ee];            // (8,512)
__device__ float g_c2q  [Bb*Cc*Ee];         // (8,1024,512)
__device__ float g_att  [(size_t)Bb*Cc*E4]; // attended (8,1024,2048)
__device__ float g_h    [(size_t)Bb*Cc*Hh]; // hidden   (8,1024,1024)

// ---------------------------------------------------------------------------
// K1: row dot products  c_w = ctx@w_c (8192 rows), q_w = qst@w_q (1024 rows)
// one warp per row, float4 loads
// ---------------------------------------------------------------------------
__global__ void k_rowdot(const float* __restrict__ ctx, const float* __restrict__ qst,
                         const float* __restrict__ wc,  const float* __restrict__ wq)
{
    int warp = (blockIdx.x * blockDim.x + threadIdx.x) >> 5;
    int lane = threadIdx.x & 31;
    const float* base; const float* w; float* out;
    if (warp < Bb*Cc) { base = ctx + (size_t)warp*Ee;          w = wc; out = g_cw + warp; }
    else              { int r = warp - Bb*Cc;
                        base = qst + (size_t)r*Ee;             w = wq; out = g_qw + r; }
    float acc = 0.f;
    #pragma unroll
    for (int i = lane*4; i < Ee; i += 128) {
        float4 a = *reinterpret_cast<const float4*>(base + i);
        float4 b = *reinterpret_cast<const float4*>(w + i);
        acc += a.x*b.x + a.y*b.y + a.z*b.z + a.w*b.w;
    }
    #pragma unroll
    for (int o = 16; o; o >>= 1) acc += __shfl_xor_sync(0xffffffffu, acc, o);
    if (lane == 0) *out = acc;
}

// ---------------------------------------------------------------------------
// K2: g_qmT[b,e,q] = question[b,q,e] * w_mult[e]   (smem transpose, 32x32)
// ---------------------------------------------------------------------------
__global__ void k_qmT(const float* __restrict__ qst, const float* __restrict__ wm)
{
    __shared__ float t[32][33];
    int b  = blockIdx.z;
    int e0 = blockIdx.x * 32, q0 = blockIdx.y * 32;
    int tx = threadIdx.x, ty = threadIdx.y;
    t[ty][tx] = qst[(size_t)b*Qq*Ee + (size_t)(q0+ty)*Ee + (e0+tx)];
    __syncthreads();
    g_qmT[(size_t)b*Ee*Qq + (size_t)(e0+ty)*Qq + (q0+tx)] = t[tx][ty] * wm[e0+ty];
}

// ---------------------------------------------------------------------------
// Generic SGEMM: C = A(MxK,row) @ B(KxN,row), 128x128x16 tile, 8x8 micro-tile.
// EPI: 0 = plain
//      1 = + rowv[z*M+r] + colv[z*N+c]            (sim bias)
//      2 = (acc + colv[c]) * rowv[r]              (bias + mask)
//      3 = relu((acc + colv[c]) * rowv[r])        (bias + mask + relu)
// ---------------------------------------------------------------------------
template <int EPI>
__global__ void __launch_bounds__(256)
sgemm128(const float* __restrict__ A, const float* __restrict__ B, float* __restrict__ C,
         int M, int N, int K, size_t sA, size_t sB, size_t sC,
         const float* __restrict__ colv, const float* __restrict__ rowv)
{
    constexpr int BM = 128, BN = 128, BK = 16, TM = 8, TN = 8;
    __shared__ float As[BK][BM];
    __shared__ float Bs[BK][BN];

    const int tid = threadIdx.x;
    const int z   = blockIdx.z;
    A += (size_t)z*sA + (size_t)blockIdx.y*BM*K;
    B += (size_t)z*sB + (size_t)blockIdx.x*BN;
    C += (size_t)z*sC + (size_t)blockIdx.y*BM*N + (size_t)blockIdx.x*BN;

    const int aRow = tid >> 2;         // 0..63
    const int aCol = (tid & 3) * 4;    // 0,4,8,12
    const int bRow = tid >> 5;         // 0..7
    const int bCol = (tid & 31) * 4;   // 0..124
    const int tRow = (tid >> 4) * TM;  // 0..120
    const int tCol = (tid & 15) * TN;  // 0..120

    float acc[TM][TN] = {};
    float rm[TM], rn[TN];

    for (int k0 = 0; k0 < K; k0 += BK) {
        #pragma unroll
        for (int off = 0; off < BM; off += 64) {
            float4 v = *reinterpret_cast<const float4*>(&A[(size_t)(aRow+off)*K + k0 + aCol]);
            As[aCol+0][aRow+off] = v.x;
            As[aCol+1][aRow+off] = v.y;
            As[aCol+2][aRow+off] = v.z;
            As[aCol+3][aRow+off] = v.w;
        }
        #pragma unroll
        for (int off = 0; off < BK; off += 8) {
            *reinterpret_cast<float4*>(&Bs[bRow+off][bCol]) =
                *reinterpret_cast<const float4*>(&B[(size_t)(k0+bRow+off)*N + bCol]);
        }
        __syncthreads();

        #pragma unroll
        for (int k = 0; k < BK; k++) {
            #pragma unroll
            for (int i = 0; i < TM; i += 4)
                *reinterpret_cast<float4*>(&rm[i]) =
                    *reinterpret_cast<const float4*>(&As[k][tRow+i]);
            #pragma unroll
            for (int j = 0; j < TN; j += 4)
                *reinterpret_cast<float4*>(&rn[j]) =
                    *reinterpret_cast<const float4*>(&Bs[k][tCol+j]);
            #pragma unroll
            for (int i = 0; i < TM; i++)
                #pragma unroll
                for (int j = 0; j < TN; j++)
                    acc[i][j] = fmaf(rm[i], rn[j], acc[i][j]);
        }
        __syncthreads();
    }

    #pragma unroll
    for (int i = 0; i < TM; i++) {
        const int gr = blockIdx.y*BM + tRow + i;
        float add_r = 0.f, mk = 1.f;
        if (EPI == 1) add_r = rowv[(size_t)z*M + gr];
        if (EPI >= 2) mk    = rowv[gr];
        #pragma unroll
        for (int j = 0; j < TN; j += 4) {
            const int gc = blockIdx.x*BN + tCol + j;
            float v0 = acc[i][j+0], v1 = acc[i][j+1], v2 = acc[i][j+2], v3 = acc[i][j+3];
            if (EPI == 1) {
                size_t cb = (size_t)z*N + gc;
                v0 += add_r + colv[cb+0]; v1 += add_r + colv[cb+1];
                v2 += add_r + colv[cb+2]; v3 += add_r + colv[cb+3];
            } else if (EPI == 2) {
                v0 = (v0 + colv[gc+0]) * mk; v1 = (v1 + colv[gc+1]) * mk;
                v2 = (v2 + colv[gc+2]) * mk; v3 = (v3 + colv[gc+3]) * mk;
            } else if (EPI == 3) {
                v0 = fmaxf((v0 + colv[gc+0]) * mk, 0.f);
                v1 = fmaxf((v1 + colv[gc+1]) * mk, 0.f);
                v2 = fmaxf((v2 + colv[gc+2]) * mk, 0.f);
                v3 = fmaxf((v3 + colv[gc+3]) * mk, 0.f);
            }
            float4 o; o.x = v0; o.y = v1; o.z = v2; o.w = v3;
            *reinterpret_cast<float4*>(&C[(size_t)(tRow+i)*N + tCol + j]) = o;
        }
    }
}

// ---------------------------------------------------------------------------
// K4: per-row softmax over q (128) on g_S in-place; g_m[row] = rowmax
// ---------------------------------------------------------------------------
__global__ void k_softmax_rows()
{
    __shared__ float sm[128];
    const int row = blockIdx.x;
    const int t   = threadIdx.x;
    float v = g_S[(size_t)row*Qq + t];
    sm[t] = v; __syncthreads();
    #pragma unroll
    for (int s = 64; s > 0; s >>= 1) { if (t < s) sm[t] = fmaxf(sm[t], sm[t+s]); __syncthreads(); }
    const float mx = sm[0];
    __syncthreads();
    float e = __expf(v - mx);
    sm[t] = e; __syncthreads();
    #pragma unroll
    for (int s = 64; s > 0; s >>= 1) { if (t < s) sm[t] += sm[t+s]; __syncthreads(); }
    const float tot = sm[0];
    g_S[(size_t)row*Qq + t] = e / tot;
    if (t == 0) g_m[row] = mx;
}

// ---------------------------------------------------------------------------
// K5: alpha[b,:] = softmax over c (1024) of g_m[b,:]
// ---------------------------------------------------------------------------
__global__ void k_alpha()
{
    __shared__ float sm[1024];
    const int b = blockIdx.x;
    const int t = threadIdx.x;
    float v = g_m[(size_t)b*Cc + t];
    sm[t] = v; __syncthreads();
    #pragma unroll
    for (int s = 512; s > 0; s >>= 1) { if (t < s) sm[t] = fmaxf(sm[t], sm[t+s]); __syncthreads(); }
    const float mx = sm[0];
    __syncthreads();
    float e = __expf(v - mx);
    sm[t] = e; __syncthreads();
    #pragma unroll
    for (int s = 512; s > 0; s >>= 1) { if (t < s) sm[t] += sm[t+s]; __syncthreads(); }
    g_alpha[(size_t)b*Cc + t] = e / sm[0];
}

// ---------------------------------------------------------------------------
// K6: q2c[b,e] = sum_c alpha[b,c] * context[b,c,e]
// ---------------------------------------------------------------------------
__global__ void k_q2c(const float* __restrict__ ctx)
{
    __shared__ float sal[Cc];
    const int b = blockIdx.y;
    const int e = blockIdx.x*128 + threadIdx.x;
    for (int i = threadIdx.x; i < Cc; i += 128) sal[i] = g_alpha[(size_t)b*Cc + i];
    __syncthreads();
    float acc = 0.f;
    const float* cp = ctx + (size_t)b*Cc*Ee + e;
    #pragma unroll 4
    for (int c = 0; c < Cc; c++) acc += sal[c] * cp[(size_t)c*Ee];
    g_q2c[(size_t)b*Ee + e] = acc;
}

// ---------------------------------------------------------------------------
// K8: build attended = [ctx, c2q, ctx*c2q, ctx*q2c]
// ---------------------------------------------------------------------------
__global__ void k_attend(const float* __restrict__ ctx)
{
    const int idx = blockIdx.x*256 + threadIdx.x;   // 0 .. 8192*512-1
    const int row = idx >> 9;                        // 0..8191
    const int e   = idx & 511;
    const int b   = row >> 10;
    float c  = ctx[idx];
    float cq = g_c2q[idx];
    float qc = g_q2c[(size_t)b*Ee + e];
    float* o = g_att + (size_t)row*E4;
    o[e]        = c;
    o[Ee  + e]  = cq;
    o[2*Ee + e] = c * cq;
    o[3*Ee + e] = c * qc;
}

// ---------------------------------------------------------------------------
// kernel_launch
// ---------------------------------------------------------------------------
extern "C" void kernel_launch(void* const* d_in, const int* in_sizes, int n_in,
                              void* d_out, int out_size)
{
    const float* ctx  = (const float*)d_in[0];  // (8,1024,512)
    const float* qst  = (const float*)d_in[1];  // (8,128,512)
    const float* mask = (const float*)d_in[2];  // (8,1024) flat 8192
    const float* wq   = (const float*)d_in[3];  // (512)
    const float* wc   = (const float*)d_in[4];  // (512)
    const float* wm   = (const float*)d_in[5];  // (512)
    const float* W1   = (const float*)d_in[6];  // (2048,1024)
    const float* b1   = (const float*)d_in[7];  // (1024)
    const float* W2   = (const float*)d_in[8];  // (1024,2048)
    const float* b2   = (const float*)d_in[9];  // (2048)
    float*       out  = (float*)d_out;          // (8,1024,2048)

    // device pointers to scratch globals (no allocation; symbol lookup only)
    void *pS, *pqmT, *pc2q, *patt, *ph, *pcw, *pqw;
    cudaGetSymbolAddress(&pS,   g_S);
    cudaGetSymbolAddress(&pqmT, g_qmT);
    cudaGetSymbolAddress(&pc2q, g_c2q);
    cudaGetSymbolAddress(&patt, g_att);
    cudaGetSymbolAddress(&ph,   g_h);
    cudaGetSymbolAddress(&pcw,  g_cw);
    cudaGetSymbolAddress(&pqw,  g_qw);

    // 1) row dots: 9216 warps, 8 warps/block
    k_rowdot<<<(Bb*Cc + Bb*Qq) / 8, 256>>>(ctx, qst, wc, wq);

    // 2) qmT transpose+scale
    k_qmT<<<dim3(Ee/32, Qq/32, Bb), dim3(32, 32)>>>(qst, wm);

    // 3) sim: S[b] = ctx[b](1024x512) @ qmT[b](512x128) + cw + qw
    sgemm128<1><<<dim3(Qq/128, Cc/128, Bb), 256>>>(
        ctx, (const float*)pqmT, (float*)pS,
        Cc, Qq, Ee, (size_t)Cc*Ee, (size_t)Ee*Qq, (size_t)Cc*Qq,
        (const float*)pqw, (const float*)pcw);

    // 4) softmax over q (in-place) + rowmax
    k_softmax_rows<<<Bb*Cc, Qq>>>();

    // 5) alpha = softmax over c of rowmax
    k_alpha<<<Bb, Cc>>>();

    // 6) q2c
    k_q2c<<<dim3(Ee/128, Bb), 128>>>(ctx);

    // 7) c2q: P[b](1024x128) @ question[b](128x512)
    sgemm128<0><<<dim3(Ee/128, Cc/128, Bb), 256>>>(
        (const float*)pS, qst, (float*)pc2q,
        Cc, Ee, Qq, (size_t)Cc*Qq, (size_t)Qq*Ee, (size_t)Cc*Ee,
        nullptr, nullptr);

    // 8) attended concat
    k_attend<<<(Bb*Cc*Ee) / 256, 256>>>(ctx);

    // 9) h = (attended @ W1 + b1) * mask      M=8192 K=2048 N=1024
    sgemm128<2><<<dim3(Hh/128, (Bb*Cc)/128, 1), 256>>>(
        (const float*)patt, W1, (float*)ph,
        Bb*Cc, Hh, E4, 0, 0, 0,
        b1, mask);

    // 10) out = relu((h @ W2 + b2) * mask)    M=8192 K=1024 N=2048
    sgemm128<3><<<dim3(E4/128, (Bb*Cc)/128, 1), 256>>>(
        (const float*)ph, W2, out,
        Bb*Cc, E4, Hh, 0, 0, 0,
        b2, mask);
}